// round 16
// baseline (speedup 1.0000x reference)
#include <cuda_runtime.h>
#include <cuda_fp16.h>
#include <cstdint>
#include <cstddef>

#define BH   32
#define SEQ  2048
#define DH   64
#define QB   64
#define KB   64
#define NQT  (SEQ/QB)      // 32
#define SK   72            // half stride
#define TSZ  (64*SK)       // 4608 halfs per tile buffer
// K bufs 0,1 at [0,2TSZ); V bufs at [2TSZ,4TSZ); Q fp16 at [4TSZ,5TSZ)
#define VOFF (2*TSZ)
#define QS_OFF (4*TSZ)
#define DYN_HALFS (5*TSZ)  // 23040 halfs = 46080 B
#define CEXP 0.180336880f  // log2(e)/8

__device__ __half g_kh[BH*SEQ*DH];
__device__ __half g_vh[BH*SEQ*DH];
// p~ scratch (fp16, A-fragment order): [bh][qt][kb][4096 halfs per 64x64 unit]
__device__ __half g_s[(size_t)BH*NQT*32*4096];

__device__ __forceinline__ uint32_t smem_u32(const void* p) {
    uint32_t a;
    asm("{ .reg .u64 t; cvta.to.shared.u64 t, %1; cvt.u32.u64 %0, t; }" : "=r"(a) : "l"(p));
    return a;
}
__device__ __forceinline__ void cpa16(uint32_t dst, const void* src) {
    asm volatile("cp.async.cg.shared.global [%0], [%1], 16;" :: "r"(dst), "l"(src));
}
#define CP_COMMIT() asm volatile("cp.async.commit_group;" ::: "memory")
#define CP_WAIT(n)  asm volatile("cp.async.wait_group %0;" :: "n"(n) : "memory")
__device__ __forceinline__ void ldm4(uint32_t* r, uint32_t addr) {
    asm volatile("ldmatrix.sync.aligned.m8n8.x4.shared.b16 {%0,%1,%2,%3}, [%4];"
        : "=r"(r[0]), "=r"(r[1]), "=r"(r[2]), "=r"(r[3]) : "r"(addr));
}
__device__ __forceinline__ void ldm4t(uint32_t* r, uint32_t addr) {
    asm volatile("ldmatrix.sync.aligned.m8n8.x4.trans.shared.b16 {%0,%1,%2,%3}, [%4];"
        : "=r"(r[0]), "=r"(r[1]), "=r"(r[2]), "=r"(r[3]) : "r"(addr));
}
__device__ __forceinline__ void mma16816(float* c, const uint32_t* a, uint32_t b0, uint32_t b1) {
    asm volatile("mma.sync.aligned.m16n8k16.row.col.f32.f16.f16.f32 "
        "{%0,%1,%2,%3}, {%4,%5,%6,%7}, {%8,%9}, {%0,%1,%2,%3};"
        : "+f"(c[0]), "+f"(c[1]), "+f"(c[2]), "+f"(c[3])
        : "r"(a[0]), "r"(a[1]), "r"(a[2]), "r"(a[3]), "r"(b0), "r"(b1));
}
__device__ __forceinline__ float ex2a(float x) {
    float r; asm("ex2.approx.f32 %0, %1;" : "=f"(r) : "f"(x)); return r;
}
__device__ __forceinline__ void stg128_cs(float* p, float4 v) {
    asm volatile("st.global.cs.v4.f32 [%0], {%1,%2,%3,%4};"
        :: "l"(p), "f"(v.x), "f"(v.y), "f"(v.z), "f"(v.w) : "memory");
}
__device__ __forceinline__ void stg64_cs(float* p, float2 v) {
    asm volatile("st.global.cs.v2.f32 [%0], {%1,%2};" :: "l"(p), "f"(v.x), "f"(v.y) : "memory");
}
__device__ __forceinline__ uint2 f4h4(float4 t) {
    __half2 h0 = __floats2half2_rn(t.x, t.y);
    __half2 h1 = __floats2half2_rn(t.z, t.w);
    uint2 r; r.x = *(uint32_t*)&h0; r.y = *(uint32_t*)&h1; return r;
}

// fp32 -> fp16 for K, V only (Q converted in-kernel)
__global__ void cvt_kernel(const float4* __restrict__ k, const float4* __restrict__ v) {
    int i = blockIdx.x * 256 + threadIdx.x;
    ((uint2*)g_kh)[i] = f4h4(k[i]);
    ((uint2*)g_vh)[i] = f4h4(v[i]);
}

__device__ __forceinline__ void load_tile_off(uint32_t sb, int halfoff, const __half* src, int tid) {
    #pragma unroll
    for (int j = 0; j < 4; j++) {
        int idx = tid + j * 128;
        int row = idx >> 3, col8 = (idx & 7) << 3;
        cpa16(sb + (uint32_t)(halfoff + row * SK + col8) * 2, src + row * DH + col8);
    }
}

// QK^T: S[8][4] = Q(16 rows) x K(64 rows)^T, B fragments via ldmatrix
__device__ __forceinline__ void qk_mma(float s[8][4], const uint32_t qa[4][4], uint32_t kfb) {
    #pragma unroll
    for (int b = 0; b < 8; b++)
        #pragma unroll
        for (int c = 0; c < 4; c++) s[b][c] = 0.f;
    #pragma unroll
    for (int ntp = 0; ntp < 4; ntp++)
        #pragma unroll
        for (int kk = 0; kk < 4; kk++) {
            uint32_t bb[4];
            ldm4(bb, kfb + (uint32_t)(ntp * 16 * SK + kk * 16) * 2);
            mma16816(s[2 * ntp + 0], qa[kk], bb[0], bb[1]);
            mma16816(s[2 * ntp + 1], qa[kk], bb[2], bb[3]);
        }
}

__global__ __launch_bounds__(128, 4) void attn_mma(
    const float* __restrict__ qg_, float* __restrict__ outg, float* __restrict__ attng)
{
    extern __shared__ __half sh[];

    const int tid  = threadIdx.x;
    const int wm   = tid >> 5, lane = tid & 31;
    const int tq   = lane >> 2, tig = lane & 3;
    const int qt   = (NQT - 1) - blockIdx.x;   // biggest work first
    const int bh   = blockIdx.y;
    const int nkb  = qt + 1;

    const float*  qg = qg_ + ((size_t)bh * SEQ + qt * QB) * DH;
    const __half* kh = g_kh + (size_t)bh * SEQ * DH;
    const __half* vh = g_vh + (size_t)bh * SEQ * DH;
    float* ag = attng + (size_t)bh * SEQ * SEQ + (size_t)(qt * QB) * SEQ;
    float* og = outg + ((size_t)bh * SEQ + qt * QB) * DH;

    const size_t sb_off = ((size_t)bh * NQT + qt) * 32 * 4096;
    const int sidx = wm * 128 + lane;

    const uint32_t sb = smem_u32(sh);
    const uint32_t kfrag_lane =
        (uint32_t)((((lane >> 4) & 1) * 8 + (lane & 7)) * SK + ((lane >> 3) & 1) * 8);

    // ---- prologue: Q fp32 -> V-buffer staging (group 0), K0 (group 1) ----
    {
        uint32_t qsb = sb + (uint32_t)VOFF * 2;   // byte base of V region (fp32 Q staging)
        #pragma unroll
        for (int j = 0; j < 8; j++) {
            int idx = tid + j * 128;
            int row = idx >> 4, c4 = (idx & 15) << 2;
            cpa16(qsb + (uint32_t)(row * 68 + c4) * 4, qg + row * DH + c4);
        }
    }
    CP_COMMIT();                                       // g0: Q
    load_tile_off(sb, 0, kh, tid); CP_COMMIT();        // g1: K0

    {   // zero strictly-upper prob region (streaming stores)
        int zc = SEQ - nkb * KB;
        if (zc > 0) {
            int zw = zc >> 2;
            float4 z = make_float4(0.f, 0.f, 0.f, 0.f);
            for (int i = tid; i < QB * zw; i += 128) {
                int r = i / zw, c = i % zw;
                stg128_cs(ag + (size_t)r * SEQ + nkb * KB + c * 4, z);
            }
        }
    }

    CP_WAIT(1);          // Q fp32 arrived (K0 may still fly)
    __syncthreads();
    {   // convert Q to fp16 into QS region
        const float* qstage = (const float*)(sh + VOFF);
        #pragma unroll
        for (int j = 0; j < 8; j++) {
            int idx = tid + j * 128;
            int row = idx >> 4, c4 = (idx & 15) << 2;
            float4 t = *(const float4*)(qstage + row * 68 + c4);
            *(uint2*)(&sh[QS_OFF + row * SK + c4]) = f4h4(t);
        }
    }
    __syncthreads();     // QS visible; V region free
    load_tile_off(sb, VOFF, vh, tid); CP_COMMIT();     // g2: V0

    uint32_t qa[4][4];
    {
        int rr = lane & 15, cc8 = (lane >> 4) << 3;
        #pragma unroll
        for (int kk = 0; kk < 4; kk++)
            ldm4(qa[kk], sb + (uint32_t)(QS_OFF + (wm * 16 + rr) * SK + kk * 16 + cc8) * 2);
    }

    float l_t[2] = {0.f, 0.f};
    float o[8][4];
    #pragma unroll
    for (int b = 0; b < 8; b++)
        #pragma unroll
        for (int c = 0; c < 4; c++) o[b][c] = 0.f;

    // ====== Fused pass A: QK -> p~ -> scratch + PV, 1 barrier/unit ======
    for (int kb = 0; kb < nkb; kb++) {
        CP_WAIT(0);          // K[kb] + V[kb] complete
        __syncthreads();     // visibility + old reads of (kb+1)&1 bufs done
        if (kb + 1 < nkb) {  // prefetch next K+V into the other buffers
            int alt = (kb + 1) & 1;
            load_tile_off(sb, alt * TSZ, kh + (size_t)(kb + 1) * KB * DH, tid);
            load_tile_off(sb, VOFF + alt * TSZ, vh + (size_t)(kb + 1) * KB * DH, tid);
            CP_COMMIT();
        }
        const uint32_t kfb = sb + (uint32_t)((kb & 1) * TSZ + kfrag_lane) * 2;
        const int vcur = VOFF + (kb & 1) * TSZ;

        float s[8][4];
        qk_mma(s, qa, kfb);

        // exp + mask + pack p~; l from the QUANTIZED p~
        bool diag = (kb == nkb - 1);
        uint32_t u[16];
        #pragma unroll
        for (int h = 0; h < 2; h++) {
            int ig = qt * QB + wm * 16 + h * 8 + tq;
            float acc = 0.f;
            #pragma unroll
            for (int nt = 0; nt < 8; nt++) {
                float p0 = ex2a(s[nt][h * 2 + 0] * CEXP);
                float p1 = ex2a(s[nt][h * 2 + 1] * CEXP);
                if (diag) {
                    int jg = kb * KB + nt * 8 + tig * 2;
                    if (jg     > ig) p0 = 0.f;
                    if (jg + 1 > ig) p1 = 0.f;
                }
                __half2 hp = __floats2half2_rn(p0, p1);
                u[nt * 2 + h] = *(uint32_t*)&hp;
                float2 q2 = __half22float2(hp);
                acc += q2.x + q2.y;
            }
            l_t[h] += acc;
        }
        {   // scratch write (read back in streaming pass by the SAME thread)
            uint4* sp = (uint4*)(g_s + sb_off + (size_t)kb * 4096);
            #pragma unroll
            for (int i = 0; i < 4; i++)
                sp[i * 32 + sidx] = make_uint4(u[i*4+0], u[i*4+1], u[i*4+2], u[i*4+3]);
        }

        // O~ += P~ @ V — fragments are u[] directly
        {
            int rr = lane & 15, cc8 = (lane >> 4) << 3;
            #pragma unroll
            for (int kt = 0; kt < 4; kt++) {
                uint32_t a[4] = { u[4*kt+0], u[4*kt+1], u[4*kt+2], u[4*kt+3] };
                #pragma unroll
                for (int nc = 0; nc < 4; nc++) {
                    uint32_t bt[4];
                    ldm4t(bt, sb + (uint32_t)(vcur + (kt * 16 + rr) * SK + nc * 16 + cc8) * 2);
                    mma16816(o[nc * 2 + 0], a, bt[0], bt[1]);
                    mma16816(o[nc * 2 + 1], a, bt[2], bt[3]);
                }
            }
        }
    }

    // ---- row inverse sums ----
    float inv[2];
    #pragma unroll
    for (int h = 0; h < 2; h++) {
        float l = l_t[h];
        l += __shfl_xor_sync(0xffffffffu, l, 1);
        l += __shfl_xor_sync(0xffffffffu, l, 2);
        inv[h] = 1.0f / l;
    }

    // ---- store O = O~ * inv ----
    #pragma unroll
    for (int nt = 0; nt < 8; nt++)
        #pragma unroll
        for (int h = 0; h < 2; h++) {
            int il = wm * 16 + h * 8 + tq;
            int jl = nt * 8 + tig * 2;
            stg64_cs(og + (size_t)il * DH + jl,
                     make_float2(o[nt][h * 2] * inv[h], o[nt][h * 2 + 1] * inv[h]));
        }

    // ====== Streaming pass: probs = p~ * inv (own data; no barriers, no smem) ======
    {
        const int il0 = wm * 16 + tq;       // h=0 row
        const int il1 = il0 + 8;            // h=1 row
        uint32_t uc[16];
        {
            const uint4* sp = (const uint4*)(g_s + sb_off);
            #pragma unroll
            for (int i = 0; i < 4; i++) {
                uint4 t = sp[i * 32 + sidx];
                uc[i*4+0] = t.x; uc[i*4+1] = t.y; uc[i*4+2] = t.z; uc[i*4+3] = t.w;
            }
        }
        for (int kb = 0; kb < nkb; kb++) {
            uint32_t un[16];
            if (kb + 1 < nkb) {
                const uint4* sp = (const uint4*)(g_s + sb_off + (size_t)(kb + 1) * 4096);
                #pragma unroll
                for (int i = 0; i < 4; i++) {
                    uint4 t = sp[i * 32 + sidx];
                    un[i*4+0] = t.x; un[i*4+1] = t.y; un[i*4+2] = t.z; un[i*4+3] = t.w;
                }
            }
            float* a0 = ag + (size_t)il0 * SEQ + kb * KB;
            float* a1 = ag + (size_t)il1 * SEQ + kb * KB;
            #pragma unroll
            for (int nt = 0; nt < 8; nt++) {
                int jl = nt * 8 + tig * 2;
                float2 x0 = __half22float2(*(__half2*)&uc[nt * 2 + 0]);
                float2 x1 = __half22float2(*(__half2*)&uc[nt * 2 + 1]);
                stg64_cs(a0 + jl, make_float2(x0.x * inv[0], x0.y * inv[0]));
                stg64_cs(a1 + jl, make_float2(x1.x * inv[1], x1.y * inv[1]));
            }
            if (kb + 1 < nkb) {
                #pragma unroll
                for (int i = 0; i < 16; i++) uc[i] = un[i];
            }
        }
    }
}

extern "C" void kernel_launch(void* const* d_in, const int* in_sizes, int n_in,
                              void* d_out, int out_size) {
    const float* q = (const float*)d_in[0];
    const float* k = (const float*)d_in[1];
    const float* v = (const float*)d_in[2];
    // d_in[3]: causal mask, handled analytically

    float* out  = (float*)d_out;
    float* attn = (float*)d_out + (size_t)BH * SEQ * DH;

    cvt_kernel<<<BH * SEQ * DH / 4 / 256, 256>>>((const float4*)k, (const float4*)v);
    cudaFuncSetAttribute(attn_mma, cudaFuncAttributeMaxDynamicSharedMemorySize, DYN_HALFS * 2);
    attn_mma<<<dim3(NQT, BH), 128, DYN_HALFS * 2>>>(q, out, attn);
}

// round 17
// speedup vs baseline: 1.0231x; 1.0231x over previous
#include <cuda_runtime.h>
#include <cuda_fp16.h>
#include <cstdint>
#include <cstddef>

#define BH   32
#define SEQ  2048
#define DH   64
#define QB   64
#define KB   64
#define NQT  (SEQ/QB)      // 32
#define SK   72            // half stride
#define TSZ  (64*SK)       // 4608 halfs per tile buffer
#define VOFF (2*TSZ)
#define QS_OFF (4*TSZ)
#define DYN_HALFS (5*TSZ)  // 46080 B
#define CEXP 0.180336880f  // log2(e)/8

__device__ __half g_kh[BH*SEQ*DH];
__device__ __half g_vh[BH*SEQ*DH];
// p~ scratch (fp16, A-fragment order): [bh][qt][kb][4096 halfs per 64x64 unit]
__device__ __half g_s[(size_t)BH*NQT*32*4096];

__device__ __forceinline__ uint32_t smem_u32(const void* p) {
    uint32_t a;
    asm("{ .reg .u64 t; cvta.to.shared.u64 t, %1; cvt.u32.u64 %0, t; }" : "=r"(a) : "l"(p));
    return a;
}
__device__ __forceinline__ void cpa16(uint32_t dst, const void* src) {
    asm volatile("cp.async.cg.shared.global [%0], [%1], 16;" :: "r"(dst), "l"(src));
}
#define CP_COMMIT() asm volatile("cp.async.commit_group;" ::: "memory")
#define CP_WAIT(n)  asm volatile("cp.async.wait_group %0;" :: "n"(n) : "memory")
__device__ __forceinline__ void ldm4(uint32_t* r, uint32_t addr) {
    asm volatile("ldmatrix.sync.aligned.m8n8.x4.shared.b16 {%0,%1,%2,%3}, [%4];"
        : "=r"(r[0]), "=r"(r[1]), "=r"(r[2]), "=r"(r[3]) : "r"(addr));
}
__device__ __forceinline__ void ldm4t(uint32_t* r, uint32_t addr) {
    asm volatile("ldmatrix.sync.aligned.m8n8.x4.trans.shared.b16 {%0,%1,%2,%3}, [%4];"
        : "=r"(r[0]), "=r"(r[1]), "=r"(r[2]), "=r"(r[3]) : "r"(addr));
}
__device__ __forceinline__ void mma16816(float* c, const uint32_t* a, uint32_t b0, uint32_t b1) {
    asm volatile("mma.sync.aligned.m16n8k16.row.col.f32.f16.f16.f32 "
        "{%0,%1,%2,%3}, {%4,%5,%6,%7}, {%8,%9}, {%0,%1,%2,%3};"
        : "+f"(c[0]), "+f"(c[1]), "+f"(c[2]), "+f"(c[3])
        : "r"(a[0]), "r"(a[1]), "r"(a[2]), "r"(a[3]), "r"(b0), "r"(b1));
}
__device__ __forceinline__ float ex2a(float x) {
    float r; asm("ex2.approx.f32 %0, %1;" : "=f"(r) : "f"(x)); return r;
}
__device__ __forceinline__ uint32_t ex2h2(uint32_t x) {
    uint32_t r; asm("ex2.approx.f16x2 %0, %1;" : "=r"(r) : "r"(x)); return r;
}
__device__ __forceinline__ void stg128_cs(float* p, float4 v) {
    asm volatile("st.global.cs.v4.f32 [%0], {%1,%2,%3,%4};"
        :: "l"(p), "f"(v.x), "f"(v.y), "f"(v.z), "f"(v.w) : "memory");
}
__device__ __forceinline__ void stg64_cs(float* p, float2 v) {
    asm volatile("st.global.cs.v2.f32 [%0], {%1,%2};" :: "l"(p), "f"(v.x), "f"(v.y) : "memory");
}
__device__ __forceinline__ uint2 f4h4(float4 t) {
    __half2 h0 = __floats2half2_rn(t.x, t.y);
    __half2 h1 = __floats2half2_rn(t.z, t.w);
    uint2 r; r.x = *(uint32_t*)&h0; r.y = *(uint32_t*)&h1; return r;
}

// fp32 -> fp16 for K, V only (Q converted in-kernel)
__global__ void cvt_kernel(const float4* __restrict__ k, const float4* __restrict__ v) {
    int i = blockIdx.x * 256 + threadIdx.x;
    ((uint2*)g_kh)[i] = f4h4(k[i]);
    ((uint2*)g_vh)[i] = f4h4(v[i]);
}

__device__ __forceinline__ void load_tile_off(uint32_t sb, int halfoff, const __half* src, int tid) {
    #pragma unroll
    for (int j = 0; j < 4; j++) {
        int idx = tid + j * 128;
        int row = idx >> 3, col8 = (idx & 7) << 3;
        cpa16(sb + (uint32_t)(halfoff + row * SK + col8) * 2, src + row * DH + col8);
    }
}

// QK^T: S[8][4] = Q(16 rows) x K(64 rows)^T, B fragments via ldmatrix
__device__ __forceinline__ void qk_mma(float s[8][4], const uint32_t qa[4][4], uint32_t kfb) {
    #pragma unroll
    for (int b = 0; b < 8; b++)
        #pragma unroll
        for (int c = 0; c < 4; c++) s[b][c] = 0.f;
    #pragma unroll
    for (int ntp = 0; ntp < 4; ntp++)
        #pragma unroll
        for (int kk = 0; kk < 4; kk++) {
            uint32_t bb[4];
            ldm4(bb, kfb + (uint32_t)(ntp * 16 * SK + kk * 16) * 2);
            mma16816(s[2 * ntp + 0], qa[kk], bb[0], bb[1]);
            mma16816(s[2 * ntp + 1], qa[kk], bb[2], bb[3]);
        }
}

__global__ __launch_bounds__(128, 4) void attn_mma(
    const float* __restrict__ qg_, float* __restrict__ outg, float* __restrict__ attng)
{
    extern __shared__ __half sh[];

    const int tid  = threadIdx.x;
    const int wm   = tid >> 5, lane = tid & 31;
    const int tq   = lane >> 2, tig = lane & 3;
    const int qt   = (NQT - 1) - blockIdx.x;   // biggest work first
    const int bh   = blockIdx.y;
    const int nkb  = qt + 1;

    const float*  qg = qg_ + ((size_t)bh * SEQ + qt * QB) * DH;
    const __half* kh = g_kh + (size_t)bh * SEQ * DH;
    const __half* vh = g_vh + (size_t)bh * SEQ * DH;
    float* ag = attng + (size_t)bh * SEQ * SEQ + (size_t)(qt * QB) * SEQ;
    float* og = outg + ((size_t)bh * SEQ + qt * QB) * DH;

    const size_t sb_off = ((size_t)bh * NQT + qt) * 32 * 4096;
    const int sidx = wm * 128 + lane;

    const uint32_t sb = smem_u32(sh);
    const uint32_t kfrag_lane =
        (uint32_t)((((lane >> 4) & 1) * 8 + (lane & 7)) * SK + ((lane >> 3) & 1) * 8);

    // ---- prologue: Q fp32 -> V-buffer staging (group 0), K0 (group 1) ----
    {
        uint32_t qsb = sb + (uint32_t)VOFF * 2;
        #pragma unroll
        for (int j = 0; j < 8; j++) {
            int idx = tid + j * 128;
            int row = idx >> 4, c4 = (idx & 15) << 2;
            cpa16(qsb + (uint32_t)(row * 68 + c4) * 4, qg + row * DH + c4);
        }
    }
    CP_COMMIT();                                       // g0: Q
    load_tile_off(sb, 0, kh, tid); CP_COMMIT();        // g1: K0

    {   // zero strictly-upper prob region (streaming stores)
        int zc = SEQ - nkb * KB;
        if (zc > 0) {
            int zw = zc >> 2;
            float4 z = make_float4(0.f, 0.f, 0.f, 0.f);
            for (int i = tid; i < QB * zw; i += 128) {
                int r = i / zw, c = i % zw;
                stg128_cs(ag + (size_t)r * SEQ + nkb * KB + c * 4, z);
            }
        }
    }

    CP_WAIT(1);
    __syncthreads();
    {   // convert Q to fp16 into QS region
        const float* qstage = (const float*)(sh + VOFF);
        #pragma unroll
        for (int j = 0; j < 8; j++) {
            int idx = tid + j * 128;
            int row = idx >> 4, c4 = (idx & 15) << 2;
            float4 t = *(const float4*)(qstage + row * 68 + c4);
            *(uint2*)(&sh[QS_OFF + row * SK + c4]) = f4h4(t);
        }
    }
    __syncthreads();
    load_tile_off(sb, VOFF, vh, tid); CP_COMMIT();     // g2: V0

    uint32_t qa[4][4];
    {
        int rr = lane & 15, cc8 = (lane >> 4) << 3;
        #pragma unroll
        for (int kk = 0; kk < 4; kk++)
            ldm4(qa[kk], sb + (uint32_t)(QS_OFF + (wm * 16 + rr) * SK + kk * 16 + cc8) * 2);
    }

    float l_t[2] = {0.f, 0.f};
    float o[8][4];
    #pragma unroll
    for (int b = 0; b < 8; b++)
        #pragma unroll
        for (int c = 0; c < 4; c++) o[b][c] = 0.f;

    // ====== Fused pass A: QK -> p~(f16x2 exp) -> scratch + PV, 1 barrier/unit ======
    for (int kb = 0; kb < nkb; kb++) {
        CP_WAIT(0);
        __syncthreads();
        if (kb + 1 < nkb) {
            int alt = (kb + 1) & 1;
            load_tile_off(sb, alt * TSZ, kh + (size_t)(kb + 1) * KB * DH, tid);
            load_tile_off(sb, VOFF + alt * TSZ, vh + (size_t)(kb + 1) * KB * DH, tid);
            CP_COMMIT();
        }
        const uint32_t kfb = sb + (uint32_t)((kb & 1) * TSZ + kfrag_lane) * 2;
        const int vcur = VOFF + (kb & 1) * TSZ;

        float s[8][4];
        qk_mma(s, qa, kfb);

        uint32_t u[16];
        if (kb < nkb - 1) {
            // non-diagonal: packed fp16 exp + HADD2 row-sum tree
            #pragma unroll
            for (int h = 0; h < 2; h++) {
                __half2 hacc = __float2half2_rn(0.f);
                #pragma unroll
                for (int nt = 0; nt < 8; nt++) {
                    __half2 hx = __floats2half2_rn(s[nt][h * 2 + 0] * CEXP,
                                                   s[nt][h * 2 + 1] * CEXP);
                    uint32_t r = ex2h2(*(uint32_t*)&hx);
                    u[nt * 2 + h] = r;
                    hacc = __hadd2(hacc, *(__half2*)&r);
                }
                float2 f = __half22float2(hacc);
                l_t[h] += f.x + f.y;
            }
        } else {
            // diagonal unit: exact fp32 path with causal masking
            #pragma unroll
            for (int h = 0; h < 2; h++) {
                int ig = qt * QB + wm * 16 + h * 8 + tq;
                float acc = 0.f;
                #pragma unroll
                for (int nt = 0; nt < 8; nt++) {
                    float p0 = ex2a(s[nt][h * 2 + 0] * CEXP);
                    float p1 = ex2a(s[nt][h * 2 + 1] * CEXP);
                    int jg = kb * KB + nt * 8 + tig * 2;
                    if (jg     > ig) p0 = 0.f;
                    if (jg + 1 > ig) p1 = 0.f;
                    __half2 hp = __floats2half2_rn(p0, p1);
                    u[nt * 2 + h] = *(uint32_t*)&hp;
                    float2 q2 = __half22float2(hp);
                    acc += q2.x + q2.y;
                }
                l_t[h] += acc;
            }
        }
        {   // scratch write (read back by the SAME thread later)
            uint4* sp = (uint4*)(g_s + sb_off + (size_t)kb * 4096);
            #pragma unroll
            for (int i = 0; i < 4; i++)
                sp[i * 32 + sidx] = make_uint4(u[i*4+0], u[i*4+1], u[i*4+2], u[i*4+3]);
        }

        // O~ += P~ @ V
        {
            int rr = lane & 15, cc8 = (lane >> 4) << 3;
            #pragma unroll
            for (int kt = 0; kt < 4; kt++) {
                uint32_t a[4] = { u[4*kt+0], u[4*kt+1], u[4*kt+2], u[4*kt+3] };
                #pragma unroll
                for (int nc = 0; nc < 4; nc++) {
                    uint32_t bt[4];
                    ldm4t(bt, sb + (uint32_t)(vcur + (kt * 16 + rr) * SK + nc * 16 + cc8) * 2);
                    mma16816(o[nc * 2 + 0], a, bt[0], bt[1]);
                    mma16816(o[nc * 2 + 1], a, bt[2], bt[3]);
                }
            }
        }
    }

    // ---- row inverse sums ----
    float inv[2];
    #pragma unroll
    for (int h = 0; h < 2; h++) {
        float l = l_t[h];
        l += __shfl_xor_sync(0xffffffffu, l, 1);
        l += __shfl_xor_sync(0xffffffffu, l, 2);
        inv[h] = 1.0f / l;
    }

    // ---- store O = O~ * inv ----
    #pragma unroll
    for (int nt = 0; nt < 8; nt++)
        #pragma unroll
        for (int h = 0; h < 2; h++) {
            int il = wm * 16 + h * 8 + tq;
            int jl = nt * 8 + tig * 2;
            stg64_cs(og + (size_t)il * DH + jl,
                     make_float2(o[nt][h * 2] * inv[h], o[nt][h * 2 + 1] * inv[h]));
        }

    // ====== Streaming pass: probs = p~ * inv (own data; no barriers, no smem) ======
    {
        const int il0 = wm * 16 + tq;
        const int il1 = il0 + 8;
        uint32_t uc[16];
        {
            const uint4* sp = (const uint4*)(g_s + sb_off);
            #pragma unroll
            for (int i = 0; i < 4; i++) {
                uint4 t = sp[i * 32 + sidx];
                uc[i*4+0] = t.x; uc[i*4+1] = t.y; uc[i*4+2] = t.z; uc[i*4+3] = t.w;
            }
        }
        for (int kb = 0; kb < nkb; kb++) {
            uint32_t un[16];
            if (kb + 1 < nkb) {
                const uint4* sp = (const uint4*)(g_s + sb_off + (size_t)(kb + 1) * 4096);
                #pragma unroll
                for (int i = 0; i < 4; i++) {
                    uint4 t = sp[i * 32 + sidx];
                    un[i*4+0] = t.x; un[i*4+1] = t.y; un[i*4+2] = t.z; un[i*4+3] = t.w;
                }
            }
            float* a0 = ag + (size_t)il0 * SEQ + kb * KB;
            float* a1 = ag + (size_t)il1 * SEQ + kb * KB;
            #pragma unroll
            for (int nt = 0; nt < 8; nt++) {
                int jl = nt * 8 + tig * 2;
                float2 x0 = __half22float2(*(__half2*)&uc[nt * 2 + 0]);
                float2 x1 = __half22float2(*(__half2*)&uc[nt * 2 + 1]);
                stg64_cs(a0 + jl, make_float2(x0.x * inv[0], x0.y * inv[0]));
                stg64_cs(a1 + jl, make_float2(x1.x * inv[1], x1.y * inv[1]));
            }
            if (kb + 1 < nkb) {
                #pragma unroll
                for (int i = 0; i < 16; i++) uc[i] = un[i];
            }
        }
    }
}

extern "C" void kernel_launch(void* const* d_in, const int* in_sizes, int n_in,
                              void* d_out, int out_size) {
    const float* q = (const float*)d_in[0];
    const float* k = (const float*)d_in[1];
    const float* v = (const float*)d_in[2];
    // d_in[3]: causal mask, handled analytically

    float* out  = (float*)d_out;
    float* attn = (float*)d_out + (size_t)BH * SEQ * DH;

    cvt_kernel<<<BH * SEQ * DH / 4 / 256, 256>>>((const float4*)k, (const float4*)v);
    cudaFuncSetAttribute(attn_mma, cudaFuncAttributeMaxDynamicSharedMemorySize, DYN_HALFS * 2);
    attn_mma<<<dim3(NQT, BH), 128, DYN_HALFS * 2>>>(q, out, attn);
}